// round 9
// baseline (speedup 1.0000x reference)
#include <cuda_runtime.h>
#include <math.h>

#define NUM_RADIUS 15
#define NUM_ANGLE 48
#define EMB 32
#define NUM_ACTIONS 4
#define NUM_COMBO (NUM_RADIUS * NUM_ANGLE)   // 720
#define TPB 256

// Bucket-pair indices. Reuses radius (=hypot) for the atan2 half-angle
// reduction: u = mn/(mx + hypot) = t/(1+sqrt(1+t^2)), u in [0, 0.4142].
// Taylor atan(u) through u^13: truncation <= u^15/15 ~ 1.2e-7 rad.
__device__ __forceinline__ void bucket_indices(float axp, float azp, float pose,
                                               float gx, float gz,
                                               int& r_idx, int& t_idx) {
    float dx = gx - axp;
    float dz = gz - azp;

    float radius = sqrtf(fmaf(dx, dx, dz * dz));
    r_idx = min((int)(radius * 0.2f), NUM_RADIUS - 1);

    float ax = fabsf(dx), ay = fabsf(dz);
    float mn = fminf(ax, ay), mx = fmaxf(ax, ay);
    float u = __fdividef(mn, mx + radius);
    float s = u * u;
    float p = 0.07692307693f;                 //  1/13
    p = fmaf(p, s, -0.09090909091f);          // -1/11
    p = fmaf(p, s,  0.11111111111f);          //  1/9
    p = fmaf(p, s, -0.14285714286f);          // -1/7
    p = fmaf(p, s,  0.2f);                    //  1/5
    p = fmaf(p, s, -0.33333333333f);          // -1/3
    float atu = fmaf(p * s, u, u);            // atan(u)
    float a = 2.0f * atu;                     // atan(mn/mx)
    if (ay > ax) a = 1.57079632679f - a;
    if (dx < 0.0f) a = 3.14159265359f - a;
    a = (dz < 0.0f) ? -a : a;                 // atan2(dz, dx)

    float deg = __fmul_rn(a, 57.29577951308232f);
    float dtg = __fsub_rn(90.0f, deg);
    float f = __fsub_rn(dtg, pose);
    float ad = fmaf(-360.0f, floorf(f * 0.0027777778f), f);
    ad = fminf(fmaxf(ad, 0.0f), 359.99997f);
    t_idx = (int)(ad * 0.13333334f);          // in [0,47] by construction
}

__global__ void __launch_bounds__(TPB)
goal_position_fused(const float4* __restrict__ agent4,  // [B,3] as float4s
                    const float4* __restrict__ goal4,   // [B,2] as float4s
                    float4* __restrict__ out,           // [B] float4
                    int n4,                              // B/4
                    const float* __restrict__ radius_table,
                    const float* __restrict__ angle_table,
                    const float* __restrict__ W,
                    const float* __restrict__ b) {
    __shared__ float  sW[2 * EMB * NUM_ACTIONS];   // 1 KB
    __shared__ float4 sLR[NUM_RADIUS];             // 240 B  (logit contrib, radius)
    __shared__ float4 sLA[NUM_ANGLE];              // 768 B  (logit contrib + bias)
    __shared__ float  sLSE[NUM_COMBO];             // 2.8 KB (log-sum-exp per pair)

    const int t = threadIdx.x;

    // ---- Prologue (once per block, all blocks concurrent) ----
    if (t < 2 * EMB * NUM_ACTIONS) sW[t] = W[t];
    __syncthreads();

    if (t < NUM_RADIUS * NUM_ACTIONS) {                 // 60 dots
        int row = t >> 2, a = t & 3;
        float s = 0.0f;
        #pragma unroll
        for (int e = 0; e < EMB; e++)
            s += __ldg(&radius_table[row * EMB + e]) * sW[e * NUM_ACTIONS + a];
        ((float*)sLR)[t] = s;
    } else if (t < (NUM_RADIUS + NUM_ANGLE) * NUM_ACTIONS) {  // 192 dots
        int k = t - NUM_RADIUS * NUM_ACTIONS;
        int row = k >> 2, a = k & 3;
        float s = __ldg(&b[a]);
        #pragma unroll
        for (int e = 0; e < EMB; e++)
            s += __ldg(&angle_table[row * EMB + e]) * sW[(EMB + e) * NUM_ACTIONS + a];
        ((float*)sLA)[k] = s;
    }
    __syncthreads();

    for (int c = t; c < NUM_COMBO; c += TPB) {
        int r = c / NUM_ANGLE;
        int ta = c - r * NUM_ANGLE;
        float4 lr = sLR[r];
        float4 la = sLA[ta];
        float l0 = lr.x + la.x, l1 = lr.y + la.y;
        float l2 = lr.z + la.z, l3 = lr.w + la.w;
        float m = fmaxf(fmaxf(l0, l1), fmaxf(l2, l3));
        float e0 = __expf(l0 - m), e1 = __expf(l1 - m);
        float e2 = __expf(l2 - m), e3 = __expf(l3 - m);
        sLSE[c] = __logf(e0 + e1 + e2 + e3) + m;
    }
    __syncthreads();

    // ---- Main loop: 4 rows/thread, 5 batched LDG.128 (MLP=5), per row:
    // 2 aligned LDS.128 + 1 LDS.32 + 4 subs. No transcendentals but the
    // index math. Streaming hints on touch-once global traffic.
    const int stride = gridDim.x * TPB;
    for (int i = blockIdx.x * TPB + t; i < n4; i += stride) {
        float4 a0 = __ldcs(&agent4[3 * i + 0]);   // x0 z0 p0 x1
        float4 a1 = __ldcs(&agent4[3 * i + 1]);   // z1 p1 x2 z2
        float4 a2 = __ldcs(&agent4[3 * i + 2]);   // p2 x3 z3 p3
        float4 g0 = __ldcs(&goal4[2 * i + 0]);    // gx0 gz0 gx1 gz1
        float4 g1 = __ldcs(&goal4[2 * i + 1]);    // gx2 gz2 gx3 gz3

        int r0, t0, r1, t1, r2, t2, r3, t3;
        bucket_indices(a0.x, a0.y, a0.z, g0.x, g0.y, r0, t0);
        bucket_indices(a0.w, a1.x, a1.y, g0.z, g0.w, r1, t1);
        bucket_indices(a1.z, a1.w, a2.x, g1.x, g1.y, r2, t2);
        bucket_indices(a2.y, a2.z, a2.w, g1.z, g1.w, r3, t3);

        float4 lr, la; float lse;

        lr = sLR[r0]; la = sLA[t0]; lse = sLSE[r0 * NUM_ANGLE + t0];
        __stcs(&out[4 * i + 0], make_float4(lr.x + la.x - lse, lr.y + la.y - lse,
                                            lr.z + la.z - lse, lr.w + la.w - lse));

        lr = sLR[r1]; la = sLA[t1]; lse = sLSE[r1 * NUM_ANGLE + t1];
        __stcs(&out[4 * i + 1], make_float4(lr.x + la.x - lse, lr.y + la.y - lse,
                                            lr.z + la.z - lse, lr.w + la.w - lse));

        lr = sLR[r2]; la = sLA[t2]; lse = sLSE[r2 * NUM_ANGLE + t2];
        __stcs(&out[4 * i + 2], make_float4(lr.x + la.x - lse, lr.y + la.y - lse,
                                            lr.z + la.z - lse, lr.w + la.w - lse));

        lr = sLR[r3]; la = sLA[t3]; lse = sLSE[r3 * NUM_ANGLE + t3];
        __stcs(&out[4 * i + 3], make_float4(lr.x + la.x - lse, lr.y + la.y - lse,
                                            lr.z + la.z - lse, lr.w + la.w - lse));
    }
}

extern "C" void kernel_launch(void* const* d_in, const int* in_sizes, int n_in,
                              void* d_out, int out_size) {
    const float* agent = (const float*)d_in[0];   // [B,3]
    const float* goal = (const float*)d_in[1];    // [B,2]
    const float* radius_table = (const float*)d_in[2];
    const float* angle_table = (const float*)d_in[3];
    const float* W = (const float*)d_in[4];
    const float* b = (const float*)d_in[5];

    int n = in_sizes[0] / 3;    // B = 2,000,000 (divisible by 4)
    int n4 = n / 4;

    int tiles = (n4 + TPB - 1) / TPB;   // 1954
    int blocks = 148 * 8;               // persistent-ish, ~1.65 iters
    if (blocks > tiles) blocks = tiles;

    goal_position_fused<<<blocks, TPB>>>((const float4*)agent,
                                         (const float4*)goal,
                                         (float4*)d_out, n4,
                                         radius_table, angle_table, W, b);
}